// round 9
// baseline (speedup 1.0000x reference)
#include <cuda_runtime.h>
#include <math.h>

#define NSQ    64
#define EPS_F  1e-6f
#define EPS2_F 1e-12f
#define TRUNC  0.1f

__device__ __forceinline__ float fast_lg2(float x){ float r; asm("lg2.approx.f32 %0, %1;":"=f"(r):"f"(x)); return r; }
__device__ __forceinline__ float fast_ex2(float x){ float r; asm("ex2.approx.f32 %0, %1;":"=f"(r):"f"(x)); return r; }
__device__ __forceinline__ float fast_rcp(float x){ float r; asm("rcp.approx.f32 %0, %1;":"=f"(r):"f"(x)); return r; }
__device__ __forceinline__ float fast_sqrt(float x){ float r; asm("sqrt.approx.f32 %0, %1;":"=f"(r):"f"(x)); return r; }

// 5 float4 per prim:
// q0 = {r00,r01,r02, ntbx}   ntb = -(R^T t)
// q1 = {r10,r11,r12, ntby}
// q2 = {r20,r21,r22, ntbz}
// q3 = {K1,K2,K3, ie2}       K1 = ie2*log2(1/sx^2), K2 = ie2*log2(1/sy^2), K3 = ie1*log2(1/sz^2)
// q4 = {ie1, e21(e2/e1), ne1h(-e1/2), pad}
#define PQ 5
#define BLOCKS_RES 1184   // 148 SMs * 8 resident blocks

__global__ void __launch_bounds__(128, 8)
superq_kernel(const float* __restrict__ raw_scale,
              const float* __restrict__ raw_exp,
              const float* __restrict__ raw_rot,
              const float* __restrict__ trans,
              const float* __restrict__ points,
              float* __restrict__ out,
              int P)
{
    __shared__ float4 sp[NSQ * PQ];
    const int tid = threadIdx.x;

    if (tid < NSQ) {
        const int i = tid;
        float qw = raw_rot[4*i+0], qx = raw_rot[4*i+1];
        float qy = raw_rot[4*i+2], qz = raw_rot[4*i+3];
        float qn = 1.0f / sqrtf(qw*qw + qx*qx + qy*qy + qz*qz);
        qw *= qn; qx *= qn; qy *= qn; qz *= qn;
        const float r00 = 1.0f - 2.0f*(qy*qy + qz*qz);
        const float r01 = 2.0f*(qx*qy - qw*qz);
        const float r02 = 2.0f*(qx*qz + qw*qy);
        const float r10 = 2.0f*(qx*qy + qw*qz);
        const float r11 = 1.0f - 2.0f*(qx*qx + qz*qz);
        const float r12 = 2.0f*(qy*qz - qw*qx);
        const float r20 = 2.0f*(qx*qz - qw*qy);
        const float r21 = 2.0f*(qy*qz + qw*qx);
        const float r22 = 1.0f - 2.0f*(qx*qx + qy*qy);
        const float tx = trans[3*i+0], ty = trans[3*i+1], tz = trans[3*i+2];
        const float ntbx = -(r00*tx + r10*ty + r20*tz);
        const float ntby = -(r01*tx + r11*ty + r21*tz);
        const float ntbz = -(r02*tx + r12*ty + r22*tz);
        const float e1 = 0.1f + 1.8f / (1.0f + expf(-raw_exp[2*i+0]));
        const float e2 = 0.1f + 1.8f / (1.0f + expf(-raw_exp[2*i+1]));
        const float ie1 = 1.0f/e1, ie2 = 1.0f/e2;
        const float L2E = 1.4426950408889634f;   // log2(e)
        const float Lx = -2.0f * raw_scale[3*i+0] * L2E;   // log2(1/sx^2)
        const float Ly = -2.0f * raw_scale[3*i+1] * L2E;
        const float Lz = -2.0f * raw_scale[3*i+2] * L2E;
        sp[i*PQ+0] = make_float4(r00, r01, r02, ntbx);
        sp[i*PQ+1] = make_float4(r10, r11, r12, ntby);
        sp[i*PQ+2] = make_float4(r20, r21, r22, ntbz);
        sp[i*PQ+3] = make_float4(ie2*Lx, ie2*Ly, ie1*Lz, ie2);
        sp[i*PQ+4] = make_float4(ie1, e2/e1, -0.5f*e1, 0.0f);
    }
    __syncthreads();

    const int stride = BLOCKS_RES * 128;

    for (int p = blockIdx.x * 128 + tid; p < P; p += stride) {

        const float px = points[3*p+0];
        const float py = points[3*p+1];
        const float pz = points[3*p+2];

        float best = TRUNC;   // upper clamp folded into init; strict-< keeps first-min
        int   bi   = 0;

        // ---- Pass 1: sdf-only argmin ----
#pragma unroll 2
        for (int i = 0; i < NSQ; i++) {
            const float4 q0 = sp[i*PQ+0];
            const float4 q1 = sp[i*PQ+1];
            const float4 q2 = sp[i*PQ+2];
            const float4 q3 = sp[i*PQ+3];
            const float4 q4 = sp[i*PQ+4];

            const float xc = q0.x*px + q1.x*py + q2.x*pz + q0.w;
            const float yc = q0.y*px + q1.y*py + q2.y*pz + q1.w;
            const float zc = q0.z*px + q1.z*py + q2.z*pz + q2.w;

            // x2 ~= max(xc^2, eps^2): fused add form (validated, same rel_err)
            const float x2 = fmaf(xc, xc, EPS2_F);
            const float y2 = fmaf(yc, yc, EPS2_F);
            const float z2 = fmaf(zc, zc, EPS2_F);

            const float r2 = x2 + y2 + z2;
            const float r0 = fast_sqrt(r2);

            const float t1 = fast_ex2(fmaf(q3.w, fast_lg2(x2), q3.x));
            const float t2 = fast_ex2(fmaf(q3.w, fast_lg2(y2), q3.y));
            const float t3 = fast_ex2(fmaf(q4.x, fast_lg2(z2), q3.z));

            const float A = t1 + t2 + EPS_F;
            const float B = fast_ex2(q4.y * fast_lg2(A)) + t3;
            const float f = fast_ex2(q4.z * fast_lg2(B));

            float s = fmaf(-f, r0, r0);        // r0*(1-f)
            s = fmaxf(s, -TRUNC);              // lower clamp only

            if (s < best) { best = s; bi = i; }
        }

        // ---- Pass 2: exact-form gradient for the winning prim ----
        {
            const float4 q0 = sp[bi*PQ+0];
            const float4 q1 = sp[bi*PQ+1];
            const float4 q2 = sp[bi*PQ+2];
            const float4 q3 = sp[bi*PQ+3];
            const float4 q4 = sp[bi*PQ+4];

            const float xc = q0.x*px + q1.x*py + q2.x*pz + q0.w;
            const float yc = q0.y*px + q1.y*py + q2.y*pz + q1.w;
            const float zc = q0.z*px + q1.z*py + q2.z*pz + q2.w;

            const float axv = fabsf(xc), ayv = fabsf(yc), azv = fabsf(zc);
            const bool mx = axv > EPS_F, my = ayv > EPS_F, mz = azv > EPS_F;
            const float X = copysignf(fmaxf(axv, EPS_F), xc);
            const float Y = copysignf(fmaxf(ayv, EPS_F), yc);
            const float Z = copysignf(fmaxf(azv, EPS_F), zc);

            const float x2 = X*X, y2 = Y*Y, z2 = Z*Z;
            const float r2  = x2 + y2 + z2;
            const float ir0 = rsqrtf(r2);
            const float r0  = r2 * ir0;

            const float t1 = fast_ex2(fmaf(q3.w, fast_lg2(x2), q3.x));
            const float t2 = fast_ex2(fmaf(q3.w, fast_lg2(y2), q3.y));
            const float t3 = fast_ex2(fmaf(q4.x, fast_lg2(z2), q3.z));

            const float A    = t1 + t2 + EPS_F;
            const float lA   = fast_lg2(A);
            const float aAp  = q4.y * lA;
            const float Apow = fast_ex2(aAp);
            const float C    = fast_ex2(aAp - lA);   // A^(e2/e1-1)
            const float B    = Apow + t3;
            const float lB   = fast_lg2(B);
            const float af   = q4.z * lB;
            const float f    = fast_ex2(af);
            const float D    = fast_ex2(af - lB);    // B^(-e1/2-1)

            const float omf = 1.0f - f;

            const float XY = X*Y, YZ = Y*Z, XZ = X*Z;
            const float rP = fast_rcp(XY * Z);
            const float iX = YZ * rP, iY = XZ * rP, iZ = XY * rP;

            const float su  = ir0 * omf;
            const float rD  = r0 * D;
            const float Kxy = rD * C;
            const float gx = mx ? fmaf(X, su, (Kxy * t1) * iX) : 0.0f;
            const float gy = my ? fmaf(Y, su, (Kxy * t2) * iY) : 0.0f;
            const float gz = mz ? fmaf(Z, su, (rD  * t3) * iZ) : 0.0f;

            const float gwx = q0.x*gx + q0.y*gy + q0.z*gz;
            const float gwy = q1.x*gx + q1.y*gy + q1.z*gz;
            const float gwz = q2.x*gx + q2.y*gy + q2.z*gz;

            const float gn  = sqrtf(gwx*gwx + gwy*gwy + gwz*gwz);
            const float inv = 1.0f / fmaxf(gn, 1e-12f);

            out[p] = best;
            float* no = out + P;
            no[3*p+0] = gwx * inv;
            no[3*p+1] = gwy * inv;
            no[3*p+2] = gwz * inv;
        }
    }
}

extern "C" void kernel_launch(void* const* d_in, const int* in_sizes, int n_in,
                              void* d_out, int out_size)
{
    const float* raw_scale = (const float*)d_in[0];
    const float* raw_exp   = (const float*)d_in[1];
    const float* raw_rot   = (const float*)d_in[2];
    const float* trans     = (const float*)d_in[3];
    const float* points    = (const float*)d_in[4];
    float* out = (float*)d_out;

    const int P = in_sizes[4] / 3;
    superq_kernel<<<BLOCKS_RES, 128>>>(raw_scale, raw_exp, raw_rot, trans,
                                       points, out, P);
}

// round 10
// speedup vs baseline: 1.1557x; 1.1557x over previous
#include <cuda_runtime.h>
#include <math.h>

#define NSQ    64
#define EPS_F  1e-6f
#define EPS2_F 1e-12f
#define TRUNC  0.1f

__device__ __forceinline__ float fast_lg2(float x){ float r; asm("lg2.approx.f32 %0, %1;":"=f"(r):"f"(x)); return r; }
__device__ __forceinline__ float fast_ex2(float x){ float r; asm("ex2.approx.f32 %0, %1;":"=f"(r):"f"(x)); return r; }
__device__ __forceinline__ float fast_rcp(float x){ float r; asm("rcp.approx.f32 %0, %1;":"=f"(r):"f"(x)); return r; }
__device__ __forceinline__ float fast_sqrt(float x){ float r; asm("sqrt.approx.f32 %0, %1;":"=f"(r):"f"(x)); return r; }

// 5 float4 per prim:
// q0 = {r00,r01,r02, ntbx}   ntb = -(R^T t)
// q1 = {r10,r11,r12, ntby}
// q2 = {r20,r21,r22, ntbz}
// q3 = {K1,K2,K3, ie2}       K1 = ie2*log2(1/sx^2), K2 = ie2*log2(1/sy^2), K3 = ie1*log2(1/sz^2)
// q4 = {ie1, e21(e2/e1), ne1h(-e1/2), pad}
#define PQ 5

__global__ void __launch_bounds__(128, 9)
superq_kernel(const float* __restrict__ raw_scale,
              const float* __restrict__ raw_exp,
              const float* __restrict__ raw_rot,
              const float* __restrict__ trans,
              const float* __restrict__ points,
              float* __restrict__ out,
              int P)
{
    __shared__ float4 sp[NSQ * PQ];
    const int tid = threadIdx.x;

    if (tid < NSQ) {
        const int i = tid;
        float qw = raw_rot[4*i+0], qx = raw_rot[4*i+1];
        float qy = raw_rot[4*i+2], qz = raw_rot[4*i+3];
        float qn = 1.0f / sqrtf(qw*qw + qx*qx + qy*qy + qz*qz);
        qw *= qn; qx *= qn; qy *= qn; qz *= qn;
        const float r00 = 1.0f - 2.0f*(qy*qy + qz*qz);
        const float r01 = 2.0f*(qx*qy - qw*qz);
        const float r02 = 2.0f*(qx*qz + qw*qy);
        const float r10 = 2.0f*(qx*qy + qw*qz);
        const float r11 = 1.0f - 2.0f*(qx*qx + qz*qz);
        const float r12 = 2.0f*(qy*qz - qw*qx);
        const float r20 = 2.0f*(qx*qz - qw*qy);
        const float r21 = 2.0f*(qy*qz + qw*qx);
        const float r22 = 1.0f - 2.0f*(qx*qx + qy*qy);
        const float tx = trans[3*i+0], ty = trans[3*i+1], tz = trans[3*i+2];
        const float ntbx = -(r00*tx + r10*ty + r20*tz);
        const float ntby = -(r01*tx + r11*ty + r21*tz);
        const float ntbz = -(r02*tx + r12*ty + r22*tz);
        const float e1 = 0.1f + 1.8f / (1.0f + expf(-raw_exp[2*i+0]));
        const float e2 = 0.1f + 1.8f / (1.0f + expf(-raw_exp[2*i+1]));
        const float ie1 = 1.0f/e1, ie2 = 1.0f/e2;
        const float L2E = 1.4426950408889634f;   // log2(e)
        const float Lx = -2.0f * raw_scale[3*i+0] * L2E;   // log2(1/sx^2)
        const float Ly = -2.0f * raw_scale[3*i+1] * L2E;
        const float Lz = -2.0f * raw_scale[3*i+2] * L2E;
        sp[i*PQ+0] = make_float4(r00, r01, r02, ntbx);
        sp[i*PQ+1] = make_float4(r10, r11, r12, ntby);
        sp[i*PQ+2] = make_float4(r20, r21, r22, ntbz);
        sp[i*PQ+3] = make_float4(ie2*Lx, ie2*Ly, ie1*Lz, ie2);
        sp[i*PQ+4] = make_float4(ie1, e2/e1, -0.5f*e1, 0.0f);
    }
    __syncthreads();

    const int p = blockIdx.x * blockDim.x + tid;
    if (p >= P) return;

    const float px = points[3*p+0];
    const float py = points[3*p+1];
    const float pz = points[3*p+2];

    float best = TRUNC;   // upper clamp folded into init; strict-< keeps first-min
    int   bi   = 0;

    // ---- Pass 1: sdf-only argmin ----
#pragma unroll 4
    for (int i = 0; i < NSQ; i++) {
        const float4 q0 = sp[i*PQ+0];
        const float4 q1 = sp[i*PQ+1];
        const float4 q2 = sp[i*PQ+2];
        const float4 q3 = sp[i*PQ+3];
        const float4 q4 = sp[i*PQ+4];

        const float xc = q0.x*px + q1.x*py + q2.x*pz + q0.w;
        const float yc = q0.y*px + q1.y*py + q2.y*pz + q1.w;
        const float zc = q0.z*px + q1.z*py + q2.z*pz + q2.w;

        // x2 ~= max(xc^2, eps^2): fused add form (validated, same rel_err)
        const float x2 = fmaf(xc, xc, EPS2_F);
        const float y2 = fmaf(yc, yc, EPS2_F);
        const float z2 = fmaf(zc, zc, EPS2_F);

        const float r2 = x2 + y2 + z2;
        const float r0 = fast_sqrt(r2);

        // u = ie*lg2(x^2) + ie*log2(1/s^2)  (scale folded into constant)
        const float t1 = fast_ex2(fmaf(q3.w, fast_lg2(x2), q3.x));
        const float t2 = fast_ex2(fmaf(q3.w, fast_lg2(y2), q3.y));
        const float t3 = fast_ex2(fmaf(q4.x, fast_lg2(z2), q3.z));

        const float A = t1 + t2 + EPS_F;
        const float B = fast_ex2(q4.y * fast_lg2(A)) + t3;
        const float f = fast_ex2(q4.z * fast_lg2(B));

        float s = fmaf(-f, r0, r0);        // r0*(1-f)
        s = fmaxf(s, -TRUNC);              // lower clamp only

        if (s < best) { best = s; bi = i; }
    }

    // ---- Pass 2: exact-form gradient for the winning prim ----
    {
        const float4 q0 = sp[bi*PQ+0];
        const float4 q1 = sp[bi*PQ+1];
        const float4 q2 = sp[bi*PQ+2];
        const float4 q3 = sp[bi*PQ+3];
        const float4 q4 = sp[bi*PQ+4];

        const float xc = q0.x*px + q1.x*py + q2.x*pz + q0.w;
        const float yc = q0.y*px + q1.y*py + q2.y*pz + q1.w;
        const float zc = q0.z*px + q1.z*py + q2.z*pz + q2.w;

        const float axv = fabsf(xc), ayv = fabsf(yc), azv = fabsf(zc);
        const bool mx = axv > EPS_F, my = ayv > EPS_F, mz = azv > EPS_F;
        const float X = copysignf(fmaxf(axv, EPS_F), xc);
        const float Y = copysignf(fmaxf(ayv, EPS_F), yc);
        const float Z = copysignf(fmaxf(azv, EPS_F), zc);

        const float x2 = X*X, y2 = Y*Y, z2 = Z*Z;
        const float r2  = x2 + y2 + z2;
        const float ir0 = rsqrtf(r2);
        const float r0  = r2 * ir0;

        const float t1 = fast_ex2(fmaf(q3.w, fast_lg2(x2), q3.x));
        const float t2 = fast_ex2(fmaf(q3.w, fast_lg2(y2), q3.y));
        const float t3 = fast_ex2(fmaf(q4.x, fast_lg2(z2), q3.z));

        const float A    = t1 + t2 + EPS_F;
        const float lA   = fast_lg2(A);
        const float aAp  = q4.y * lA;
        const float Apow = fast_ex2(aAp);
        const float C    = fast_ex2(aAp - lA);   // A^(e2/e1-1)
        const float B    = Apow + t3;
        const float lB   = fast_lg2(B);
        const float af   = q4.z * lB;
        const float f    = fast_ex2(af);
        const float D    = fast_ex2(af - lB);    // B^(-e1/2-1)

        const float omf = 1.0f - f;

        const float XY = X*Y, YZ = Y*Z, XZ = X*Z;
        const float rP = fast_rcp(XY * Z);
        const float iX = YZ * rP, iY = XZ * rP, iZ = XY * rP;

        const float su  = ir0 * omf;
        const float rD  = r0 * D;
        const float Kxy = rD * C;
        const float gx = mx ? fmaf(X, su, (Kxy * t1) * iX) : 0.0f;
        const float gy = my ? fmaf(Y, su, (Kxy * t2) * iY) : 0.0f;
        const float gz = mz ? fmaf(Z, su, (rD  * t3) * iZ) : 0.0f;

        const float gwx = q0.x*gx + q0.y*gy + q0.z*gz;
        const float gwy = q1.x*gx + q1.y*gy + q1.z*gz;
        const float gwz = q2.x*gx + q2.y*gy + q2.z*gz;

        const float gn  = sqrtf(gwx*gwx + gwy*gwy + gwz*gwz);
        const float inv = 1.0f / fmaxf(gn, 1e-12f);

        out[p] = best;
        float* no = out + P;
        no[3*p+0] = gwx * inv;
        no[3*p+1] = gwy * inv;
        no[3*p+2] = gwz * inv;
    }
}

extern "C" void kernel_launch(void* const* d_in, const int* in_sizes, int n_in,
                              void* d_out, int out_size)
{
    const float* raw_scale = (const float*)d_in[0];
    const float* raw_exp   = (const float*)d_in[1];
    const float* raw_rot   = (const float*)d_in[2];
    const float* trans     = (const float*)d_in[3];
    const float* points    = (const float*)d_in[4];
    float* out = (float*)d_out;

    const int P = in_sizes[4] / 3;
    const int threads = 128;
    const int blocks  = (P + threads - 1) / threads;
    superq_kernel<<<blocks, threads>>>(raw_scale, raw_exp, raw_rot, trans,
                                       points, out, P);
}